// round 5
// baseline (speedup 1.0000x reference)
#include <cuda_runtime.h>
#include <cstdint>

// ColumnConsistencyLoss, single fused persistent kernel.
// loss = mean over columns with n>1 of (q_c - |s_c|^2/n_c) / (n_c * C)
//   n_c = #valid tokens in column c
//   s_c = sum over those tokens of softmax(logits_row)   (length-C vector)
//   q_c = sum over those tokens of sum_j softmax^2
// (identity: sum of squared deviations = q - |s|^2/n)

#define C_DIM     128
#define NCTA      128
#define NWARPS    16
#define NTHREADS  (NWARPS * 32)
#define MAX_TOK   131072
#define MAX_LIST  8192
#define DET_WORDS 2048        // 8KB detection window (read by every CTA)

__device__ unsigned char g_packed[MAX_TOK];
__device__ float    g_total;
__device__ int      g_cnt;
__device__ unsigned g_done;
__device__ unsigned g_bar;

// Process D tokens per warp with interleaved (latency-hidden) reductions.
// Lane holds dims [4*lane .. 4*lane+3] of each token's row.
template<int D>
__device__ __forceinline__ void proc_batch(const float4* __restrict__ lg,
                                           const int* __restrict__ s_list,
                                           int k, float4& acc, float& sq)
{
    float4 v[D];
    #pragma unroll
    for (int j = 0; j < D; j++) v[j] = lg[s_list[k + j * 16] * 32];

    float z[D];
    #pragma unroll
    for (int j = 0; j < D; j++) {
        v[j].x = __expf(v[j].x);
        v[j].y = __expf(v[j].y);
        v[j].z = __expf(v[j].z);
        v[j].w = __expf(v[j].w);
        z[j] = (v[j].x + v[j].y) + (v[j].z + v[j].w);
    }
    // 5-step butterfly over D independent chains (latencies overlap)
    #pragma unroll
    for (int off = 16; off; off >>= 1) {
        #pragma unroll
        for (int j = 0; j < D; j++)
            z[j] += __shfl_xor_sync(0xffffffffu, z[j], off);
    }
    #pragma unroll
    for (int j = 0; j < D; j++) {
        float r = __fdividef(1.0f, z[j]);
        float p0 = v[j].x * r, p1 = v[j].y * r;
        float p2 = v[j].z * r, p3 = v[j].w * r;
        acc.x += p0; acc.y += p1; acc.z += p2; acc.w += p3;
        sq = fmaf(p0, p0, sq); sq = fmaf(p1, p1, sq);
        sq = fmaf(p2, p2, sq); sq = fmaf(p3, p3, sq);
    }
}

__global__ void __launch_bounds__(NTHREADS, 1)
fused_kernel(const float* __restrict__ logits, const int* __restrict__ seg,
             const void* __restrict__ mask, float* __restrict__ out, int n)
{
    __shared__ int   s_list[MAX_LIST];
    __shared__ float s_all[NWARPS * C_DIM];
    __shared__ float s_sq[NWARPS];
    __shared__ float s_red[4];
    __shared__ int   s_cnt;

    int tid  = threadIdx.x;
    int lane = tid & 31;
    int warp = tid >> 5;
    int bid  = blockIdx.x;
    int c    = bid;

    if (tid == 0) s_cnt = 0;

    // ---- Phase 0: redundant local mask-dtype detection (no global state). ----
    const unsigned* mw = (const unsigned*)mask;
    int detw = min(DET_WORDS, n >> 2);
    int f_gt1 = 0, f_off = 0;
    for (int i = tid; i < detw; i += NTHREADS) {
        unsigned w = mw[i];
        f_gt1 |= ((w & 0xFEFEFEFEu) != 0u);   // some byte >= 2   -> float32 mask
        f_off |= ((w & 0xFFFFFF00u) != 0u);   // nonzero byte 1..3 -> uint8 mask
    }
    int m_gt1 = __syncthreads_or(f_gt1);
    int m_off = __syncthreads_or(f_off);

    // ---- Phase 1: pack (seg | valid<<7) into bytes, 4 tokens per word. ----
    {
        unsigned* pw = (unsigned*)g_packed;
        const int4* sg4 = (const int4*)seg;
        int nw4 = n >> 2;
        int stride = NCTA * NTHREADS;
        int start = bid * NTHREADS + tid;
        if (m_gt1) {
            const float4* mf4 = (const float4*)mask;
            for (int w = start; w < nw4; w += stride) {
                float4 m4 = mf4[w]; int4 s4 = sg4[w];
                unsigned b0 = (unsigned)(s4.x & 127) | ((m4.x != 0.0f) ? 0x80u : 0u);
                unsigned b1 = (unsigned)(s4.y & 127) | ((m4.y != 0.0f) ? 0x80u : 0u);
                unsigned b2 = (unsigned)(s4.z & 127) | ((m4.z != 0.0f) ? 0x80u : 0u);
                unsigned b3 = (unsigned)(s4.w & 127) | ((m4.w != 0.0f) ? 0x80u : 0u);
                pw[w] = b0 | (b1 << 8) | (b2 << 16) | (b3 << 24);
            }
        } else if (m_off) {
            const unsigned* mu = (const unsigned*)mask;
            for (int w = start; w < nw4; w += stride) {
                unsigned m4 = mu[w]; int4 s4 = sg4[w];
                unsigned b0 = (unsigned)(s4.x & 127) | (((m4      ) & 0xFFu) ? 0x80u : 0u);
                unsigned b1 = (unsigned)(s4.y & 127) | (((m4 >> 8 ) & 0xFFu) ? 0x80u : 0u);
                unsigned b2 = (unsigned)(s4.z & 127) | (((m4 >> 16) & 0xFFu) ? 0x80u : 0u);
                unsigned b3 = (unsigned)(s4.w & 127) | (((m4 >> 24) & 0xFFu) ? 0x80u : 0u);
                pw[w] = b0 | (b1 << 8) | (b2 << 16) | (b3 << 24);
            }
        } else {
            const int4* mi4 = (const int4*)mask;
            for (int w = start; w < nw4; w += stride) {
                int4 m4 = mi4[w]; int4 s4 = sg4[w];
                unsigned b0 = (unsigned)(s4.x & 127) | ((m4.x != 0) ? 0x80u : 0u);
                unsigned b1 = (unsigned)(s4.y & 127) | ((m4.y != 0) ? 0x80u : 0u);
                unsigned b2 = (unsigned)(s4.z & 127) | ((m4.z != 0) ? 0x80u : 0u);
                unsigned b3 = (unsigned)(s4.w & 127) | ((m4.w != 0) ? 0x80u : 0u);
                pw[w] = b0 | (b1 << 8) | (b2 << 16) | (b3 << 24);
            }
        }
        for (int i = (nw4 << 2) + start; i < n; i += stride) {   // tail
            int valid;
            if (m_gt1)      valid = (((const float*)mask)[i] != 0.0f);
            else if (m_off) valid = (((const unsigned char*)mask)[i] != 0);
            else            valid = (((const int*)mask)[i] != 0);
            g_packed[i] = (unsigned char)((seg[i] & 127) | (valid << 7));
        }
    }

    // ---- Grid barrier (all 128 CTAs co-resident on 148 SMs). ----
    __syncthreads();
    if (tid == 0) {
        __threadfence();                       // publish g_packed
        atomicAdd(&g_bar, 1u);
        while (*((volatile unsigned*)&g_bar) < (unsigned)NCTA) __nanosleep(32);
        __threadfence();                       // acquire
    }
    __syncthreads();

    // ---- Phase 2: compaction — CTA c gathers ids of tokens in column c. ----
    {
        unsigned tgt4 = (0x80u | (unsigned)c) * 0x01010101u;
        const uint4* pq = (const uint4*)g_packed;
        int nq = n >> 4;
        for (int i = tid; i < nq; i += NTHREADS) {
            uint4 q4 = pq[i];
            unsigned e0 = __vcmpeq4(q4.x, tgt4);
            unsigned e1 = __vcmpeq4(q4.y, tgt4);
            unsigned e2 = __vcmpeq4(q4.z, tgt4);
            unsigned e3 = __vcmpeq4(q4.w, tgt4);
            if (e0 | e1 | e2 | e3) {
                int base = 16 * i;
                #pragma unroll
                for (int b = 0; b < 4; b++) {
                    if ((e0 >> (8 * b)) & 1u) { int p = atomicAdd(&s_cnt, 1); if (p < MAX_LIST) s_list[p] = base + b; }
                    if ((e1 >> (8 * b)) & 1u) { int p = atomicAdd(&s_cnt, 1); if (p < MAX_LIST) s_list[p] = base + 4 + b; }
                    if ((e2 >> (8 * b)) & 1u) { int p = atomicAdd(&s_cnt, 1); if (p < MAX_LIST) s_list[p] = base + 8 + b; }
                    if ((e3 >> (8 * b)) & 1u) { int p = atomicAdd(&s_cnt, 1); if (p < MAX_LIST) s_list[p] = base + 12 + b; }
                }
            }
        }
        for (int i = (nq << 4) + tid; i < n; i += NTHREADS) {    // tail
            if (g_packed[i] == (unsigned char)(0x80u | (unsigned)c)) {
                int p = atomicAdd(&s_cnt, 1);
                if (p < MAX_LIST) s_list[p] = i;
            }
        }
    }
    __syncthreads();
    int cnt = min(s_cnt, MAX_LIST);

    // ---- Phase 3: warp-per-token softmax, 8-deep batches, interleaved chains. ----
    float4 acc = make_float4(0.f, 0.f, 0.f, 0.f);
    float  sq  = 0.f;
    const float4* lg = ((const float4*)logits) + lane;

    int k = warp;
    for (; k + 7 * 16 < cnt; k += 8 * 16)
        proc_batch<8>(lg, s_list, k, acc, sq);
    if (k + 3 * 16 < cnt) { proc_batch<4>(lg, s_list, k, acc, sq); k += 4 * 16; }
    if (k + 16     < cnt) { proc_batch<2>(lg, s_list, k, acc, sq); k += 2 * 16; }
    if (k          < cnt) { proc_batch<1>(lg, s_list, k, acc, sq); }

    // ---- Phase 4: combine warp partials -> column scalar -> global scalar. ----
    ((float4*)s_all)[warp * 32 + lane] = acc;
    sq += __shfl_xor_sync(0xffffffffu, sq, 16);
    sq += __shfl_xor_sync(0xffffffffu, sq, 8);
    sq += __shfl_xor_sync(0xffffffffu, sq, 4);
    sq += __shfl_xor_sync(0xffffffffu, sq, 2);
    sq += __shfl_xor_sync(0xffffffffu, sq, 1);
    if (lane == 0) s_sq[warp] = sq;
    __syncthreads();

    float v2n = 0.f;
    if (tid < C_DIM) {
        float sj = 0.f;
        #pragma unroll
        for (int w = 0; w < NWARPS; w++) sj += s_all[w * C_DIM + tid];
        v2n = sj * sj;
    }
    v2n += __shfl_xor_sync(0xffffffffu, v2n, 16);
    v2n += __shfl_xor_sync(0xffffffffu, v2n, 8);
    v2n += __shfl_xor_sync(0xffffffffu, v2n, 4);
    v2n += __shfl_xor_sync(0xffffffffu, v2n, 2);
    v2n += __shfl_xor_sync(0xffffffffu, v2n, 1);
    if (tid < C_DIM && lane == 0) s_red[warp] = v2n;
    __syncthreads();

    if (tid == 0) {
        float snorm2 = (s_red[0] + s_red[1]) + (s_red[2] + s_red[3]);
        float q = 0.f;
        #pragma unroll
        for (int w = 0; w < NWARPS; w++) q += s_sq[w];
        float fn = (float)cnt;
        if (cnt > 1) {
            float var = (q - snorm2 / fn) / (fn * (float)C_DIM);
            atomicAdd(&g_total, var);
            atomicAdd(&g_cnt, 1);
        }
        __threadfence();
        unsigned d = atomicAdd(&g_done, 1u);
        if (d == (unsigned)(NCTA - 1)) {
            float tot = atomicExch(&g_total, 0.f);
            int   cc  = atomicExch(&g_cnt, 0);
            out[0] = (cc > 0) ? (tot / (float)cc) : 0.f;
            g_bar  = 0u;                 // reset for next graph replay
            atomicExch(&g_done, 0u);
        }
    }
}

extern "C" void kernel_launch(void* const* d_in, const int* in_sizes, int n_in,
                              void* d_out, int out_size) {
    const float* logits = (const float*)d_in[0];
    const int*   seg    = (const int*)d_in[1];
    const void*  mask   = d_in[2];
    int n = in_sizes[1];                 // B*T tokens
    (void)n_in; (void)out_size;

    fused_kernel<<<NCTA, NTHREADS>>>(logits, seg, mask, (float*)d_out, n);
}

// round 6
// speedup vs baseline: 1.1994x; 1.1994x over previous
#include <cuda_runtime.h>
#include <cstdint>

// ColumnConsistencyLoss, single fused persistent kernel.
// loss = mean over columns with n>1 of (q_c - |s_c|^2/n_c) / (n_c * C)
//   n_c = #valid tokens in column c
//   s_c = sum over those tokens of softmax(logits_row)   (length-C vector)
//   q_c = sum over those tokens of sum_j softmax^2
// (identity: sum of squared deviations = q - |s|^2/n)

#define C_DIM     128
#define NCTA      128
#define NWARPS    32
#define NTHREADS  (NWARPS * 32)     // 1024 threads, 50% occ
#define MAX_TOK   131072
#define MAX_LIST  8192
#define DET_WORDS 2048              // 8KB detection window (read by every CTA)

__device__ unsigned char g_packed[MAX_TOK];
__device__ float    g_total;
__device__ int      g_cnt;
__device__ unsigned g_done;
__device__ unsigned g_bar;

// Process D tokens per warp. Indices prefetched, loads issued back-to-back,
// independent reduction chains interleaved. Lane holds dims [4*lane..4*lane+3].
template<int D>
__device__ __forceinline__ void proc_batch(const float4* __restrict__ lg,
                                           const int* __restrict__ s_list,
                                           int k, float4& acc, float& sq)
{
    int idx[D];
    #pragma unroll
    for (int j = 0; j < D; j++) idx[j] = s_list[k + j * NWARPS];
    float4 v[D];
    #pragma unroll
    for (int j = 0; j < D; j++) v[j] = lg[idx[j] * 32];

    float z[D];
    #pragma unroll
    for (int j = 0; j < D; j++) {
        v[j].x = __expf(v[j].x);
        v[j].y = __expf(v[j].y);
        v[j].z = __expf(v[j].z);
        v[j].w = __expf(v[j].w);
        z[j] = (v[j].x + v[j].y) + (v[j].z + v[j].w);
    }
    #pragma unroll
    for (int off = 16; off; off >>= 1) {
        #pragma unroll
        for (int j = 0; j < D; j++)
            z[j] += __shfl_xor_sync(0xffffffffu, z[j], off);
    }
    #pragma unroll
    for (int j = 0; j < D; j++) {
        float r = __fdividef(1.0f, z[j]);
        float p0 = v[j].x * r, p1 = v[j].y * r;
        float p2 = v[j].z * r, p3 = v[j].w * r;
        acc.x += p0; acc.y += p1; acc.z += p2; acc.w += p3;
        sq = fmaf(p0, p0, sq); sq = fmaf(p1, p1, sq);
        sq = fmaf(p2, p2, sq); sq = fmaf(p3, p3, sq);
    }
}

__global__ void __launch_bounds__(NTHREADS, 1)
fused_kernel(const float* __restrict__ logits, const int* __restrict__ seg,
             const void* __restrict__ mask, float* __restrict__ out, int n)
{
    __shared__ int   s_list[MAX_LIST];        // 32 KB; reused as s_all later
    __shared__ float s_sq[NWARPS];
    __shared__ float s_red[4];
    __shared__ int   s_cnt;

    int tid  = threadIdx.x;
    int lane = tid & 31;
    int warp = tid >> 5;
    int bid  = blockIdx.x;
    int c    = bid;

    if (tid == 0) s_cnt = 0;

    // ---- Phase 0: redundant local mask-dtype detection (no global state). ----
    const unsigned* mw = (const unsigned*)mask;
    int detw = min(DET_WORDS, n >> 2);
    int f_gt1 = 0, f_off = 0;
    for (int i = tid; i < detw; i += NTHREADS) {
        unsigned w = mw[i];
        f_gt1 |= ((w & 0xFEFEFEFEu) != 0u);   // some byte >= 2   -> float32 mask
        f_off |= ((w & 0xFFFFFF00u) != 0u);   // nonzero byte 1..3 -> uint8 mask
    }
    int m_gt1 = __syncthreads_or(f_gt1);
    int m_off = __syncthreads_or(f_off);

    // ---- Phase 1: pack (seg | valid<<7) into bytes, 4 tokens per word. ----
    {
        unsigned* pw = (unsigned*)g_packed;
        const int4* sg4 = (const int4*)seg;
        int nw4 = n >> 2;
        int stride = NCTA * NTHREADS;
        int start = bid * NTHREADS + tid;
        if (m_gt1) {
            const float4* mf4 = (const float4*)mask;
            for (int w = start; w < nw4; w += stride) {
                float4 m4 = mf4[w]; int4 s4 = sg4[w];
                unsigned b0 = (unsigned)(s4.x & 127) | ((m4.x != 0.0f) ? 0x80u : 0u);
                unsigned b1 = (unsigned)(s4.y & 127) | ((m4.y != 0.0f) ? 0x80u : 0u);
                unsigned b2 = (unsigned)(s4.z & 127) | ((m4.z != 0.0f) ? 0x80u : 0u);
                unsigned b3 = (unsigned)(s4.w & 127) | ((m4.w != 0.0f) ? 0x80u : 0u);
                pw[w] = b0 | (b1 << 8) | (b2 << 16) | (b3 << 24);
            }
        } else if (m_off) {
            const unsigned* mu = (const unsigned*)mask;
            for (int w = start; w < nw4; w += stride) {
                unsigned m4 = mu[w]; int4 s4 = sg4[w];
                unsigned b0 = (unsigned)(s4.x & 127) | (((m4      ) & 0xFFu) ? 0x80u : 0u);
                unsigned b1 = (unsigned)(s4.y & 127) | (((m4 >> 8 ) & 0xFFu) ? 0x80u : 0u);
                unsigned b2 = (unsigned)(s4.z & 127) | (((m4 >> 16) & 0xFFu) ? 0x80u : 0u);
                unsigned b3 = (unsigned)(s4.w & 127) | (((m4 >> 24) & 0xFFu) ? 0x80u : 0u);
                pw[w] = b0 | (b1 << 8) | (b2 << 16) | (b3 << 24);
            }
        } else {
            const int4* mi4 = (const int4*)mask;
            for (int w = start; w < nw4; w += stride) {
                int4 m4 = mi4[w]; int4 s4 = sg4[w];
                unsigned b0 = (unsigned)(s4.x & 127) | ((m4.x != 0) ? 0x80u : 0u);
                unsigned b1 = (unsigned)(s4.y & 127) | ((m4.y != 0) ? 0x80u : 0u);
                unsigned b2 = (unsigned)(s4.z & 127) | ((m4.z != 0) ? 0x80u : 0u);
                unsigned b3 = (unsigned)(s4.w & 127) | ((m4.w != 0) ? 0x80u : 0u);
                pw[w] = b0 | (b1 << 8) | (b2 << 16) | (b3 << 24);
            }
        }
        for (int i = (nw4 << 2) + start; i < n; i += stride) {   // tail
            int valid;
            if (m_gt1)      valid = (((const float*)mask)[i] != 0.0f);
            else if (m_off) valid = (((const unsigned char*)mask)[i] != 0);
            else            valid = (((const int*)mask)[i] != 0);
            g_packed[i] = (unsigned char)((seg[i] & 127) | (valid << 7));
        }
    }

    // ---- Grid barrier (all 128 CTAs co-resident on 148 SMs). ----
    __syncthreads();
    if (tid == 0) {
        __threadfence();                       // publish g_packed
        atomicAdd(&g_bar, 1u);
        while (*((volatile unsigned*)&g_bar) < (unsigned)NCTA) __nanosleep(32);
        __threadfence();                       // acquire
    }
    __syncthreads();

    // ---- Phase 2: compaction — CTA c gathers ids of tokens in column c. ----
    {
        unsigned tgt4 = (0x80u | (unsigned)c) * 0x01010101u;
        const uint4* pq = (const uint4*)g_packed;
        int nq = n >> 4;
        for (int i = tid; i < nq; i += NTHREADS) {
            uint4 q4 = pq[i];
            unsigned e0 = __vcmpeq4(q4.x, tgt4);
            unsigned e1 = __vcmpeq4(q4.y, tgt4);
            unsigned e2 = __vcmpeq4(q4.z, tgt4);
            unsigned e3 = __vcmpeq4(q4.w, tgt4);
            if (e0 | e1 | e2 | e3) {
                int base = 16 * i;
                #pragma unroll
                for (int b = 0; b < 4; b++) {
                    if ((e0 >> (8 * b)) & 1u) { int p = atomicAdd(&s_cnt, 1); if (p < MAX_LIST) s_list[p] = base + b; }
                    if ((e1 >> (8 * b)) & 1u) { int p = atomicAdd(&s_cnt, 1); if (p < MAX_LIST) s_list[p] = base + 4 + b; }
                    if ((e2 >> (8 * b)) & 1u) { int p = atomicAdd(&s_cnt, 1); if (p < MAX_LIST) s_list[p] = base + 8 + b; }
                    if ((e3 >> (8 * b)) & 1u) { int p = atomicAdd(&s_cnt, 1); if (p < MAX_LIST) s_list[p] = base + 12 + b; }
                }
            }
        }
        for (int i = (nq << 4) + tid; i < n; i += NTHREADS) {    // tail
            if (g_packed[i] == (unsigned char)(0x80u | (unsigned)c)) {
                int p = atomicAdd(&s_cnt, 1);
                if (p < MAX_LIST) s_list[p] = i;
            }
        }
    }
    __syncthreads();
    int cnt = min(s_cnt, MAX_LIST);

    // ---- Phase 3: warp-per-token softmax, depth-4 batches, 32 warps. ----
    float4 acc = make_float4(0.f, 0.f, 0.f, 0.f);
    float  sq  = 0.f;
    const float4* lg = ((const float4*)logits) + lane;

    int k = warp;
    for (; k + 3 * NWARPS < cnt; k += 4 * NWARPS)
        proc_batch<4>(lg, s_list, k, acc, sq);
    if (k + NWARPS < cnt) { proc_batch<2>(lg, s_list, k, acc, sq); k += 2 * NWARPS; }
    if (k          < cnt) { proc_batch<1>(lg, s_list, k, acc, sq); }

    // ---- Phase 4: combine warp partials -> column scalar -> global scalar. ----
    __syncthreads();                       // s_list dead; reuse its storage
    float* s_all = (float*)s_list;         // NWARPS * C_DIM floats = 16 KB
    ((float4*)s_all)[warp * 32 + lane] = acc;
    sq += __shfl_xor_sync(0xffffffffu, sq, 16);
    sq += __shfl_xor_sync(0xffffffffu, sq, 8);
    sq += __shfl_xor_sync(0xffffffffu, sq, 4);
    sq += __shfl_xor_sync(0xffffffffu, sq, 2);
    sq += __shfl_xor_sync(0xffffffffu, sq, 1);
    if (lane == 0) s_sq[warp] = sq;
    __syncthreads();

    float v2n = 0.f;
    if (tid < C_DIM) {
        float sj = 0.f;
        #pragma unroll
        for (int w = 0; w < NWARPS; w++) sj += s_all[w * C_DIM + tid];
        v2n = sj * sj;
    }
    v2n += __shfl_xor_sync(0xffffffffu, v2n, 16);
    v2n += __shfl_xor_sync(0xffffffffu, v2n, 8);
    v2n += __shfl_xor_sync(0xffffffffu, v2n, 4);
    v2n += __shfl_xor_sync(0xffffffffu, v2n, 2);
    v2n += __shfl_xor_sync(0xffffffffu, v2n, 1);
    if (tid < C_DIM && lane == 0) s_red[warp] = v2n;
    __syncthreads();

    if (tid == 0) {
        float snorm2 = (s_red[0] + s_red[1]) + (s_red[2] + s_red[3]);
        float q = 0.f;
        #pragma unroll
        for (int w = 0; w < NWARPS; w++) q += s_sq[w];
        float fn = (float)cnt;
        if (cnt > 1) {
            float var = (q - snorm2 / fn) / (fn * (float)C_DIM);
            atomicAdd(&g_total, var);
            atomicAdd(&g_cnt, 1);
        }
        __threadfence();
        unsigned d = atomicAdd(&g_done, 1u);
        if (d == (unsigned)(NCTA - 1)) {
            float tot = atomicExch(&g_total, 0.f);
            int   cc  = atomicExch(&g_cnt, 0);
            out[0] = (cc > 0) ? (tot / (float)cc) : 0.f;
            g_bar  = 0u;                 // reset for next graph replay
            atomicExch(&g_done, 0u);
        }
    }
}

extern "C" void kernel_launch(void* const* d_in, const int* in_sizes, int n_in,
                              void* d_out, int out_size) {
    const float* logits = (const float*)d_in[0];
    const int*   seg    = (const int*)d_in[1];
    const void*  mask   = d_in[2];
    int n = in_sizes[1];                 // B*T tokens
    (void)n_in; (void)out_size;

    fused_kernel<<<NCTA, NTHREADS>>>(logits, seg, mask, (float*)d_out, n);
}